// round 15
// baseline (speedup 1.0000x reference)
#include <cuda_runtime.h>
#include <cstdint>

// Problem constants
#define B_TOTAL 1024
#define T_PRED  24
#define FEAT    15
#define FILT    64
#define LENC    168
#define NDIL    6

// Kernel config
#define BROWS   8     // batch rows per block
#define NBLK    (B_TOTAL / BROWS)   // 128
#define NT      512
#define KW      68    // padded row stride (floats) for transposed weights

static __device__ __forceinline__ float fast_tanh(float x) {
    float e;
    asm("ex2.approx.f32 %0, %1;" : "=f"(e) : "f"(x * 2.8853900817779268f)); // exp(2x)
    float r;
    asm("rcp.approx.f32 %0, %1;" : "=f"(r) : "f"(e + 1.0f));
    return fmaf(-2.0f, r, 1.0f);          // 1 - 2/(e^{2x}+1)
}
static __device__ __forceinline__ float fast_sigmoid(float x) {
    float e;
    asm("ex2.approx.f32 %0, %1;" : "=f"(e) : "f"(-x * 1.4426950408889634f)); // exp(-x)
    float r;
    asm("rcp.approx.f32 %0, %1;" : "=f"(r) : "f"(e + 1.0f));
    return r;                              // 1/(1+e^{-x})
}

static __device__ __forceinline__ void dot4(float& acc, const float4& v, const float4& u) {
    acc = fmaf(v.x, u.x, acc);
    acc = fmaf(v.y, u.y, acc);
    acc = fmaf(v.z, u.z, acc);
    acc = fmaf(v.w, u.w, acc);
}
// acc += s * w (componentwise)
static __device__ __forceinline__ void fma4s(float4& acc, float s, const float4& w) {
    acc.x = fmaf(s, w.x, acc.x);
    acc.y = fmaf(s, w.y, acc.y);
    acc.z = fmaf(s, w.z, acc.z);
    acc.w = fmaf(s, w.w, acc.w);
}

#define BAR256() asm volatile("bar.sync 1, 256;" ::: "memory")

// ---- shared memory layout (float offsets) ----
#define OFF_W2T  0
#define OFF_W3T  (128*KW)
#define OFF_W4T  (2*128*KW)
#define OFF_W1   (3*128*KW)            // 26112
#define OFF_W6   (OFF_W1 + 1024)
#define OFF_B1   (OFF_W6 + 128)
#define OFF_B2   (OFF_B1 + 64)
#define OFF_B4   (OFF_B2 + 128)
#define OFF_B5   (OFF_B4 + 128)
#define OFF_B6   (OFF_B5 + 128)
#define OFF_RING (OFF_B6 + 8)          // 31 slices * 512 floats (d=1,2,4,8,16 rings)
#define OFF_ENC5 (OFF_RING + 31*512)   // d=32 encoder stage
#define OFF_INP  (OFF_ENC5 + 512)      // inputs   [row*64+j]
#define OFF_GAT  (OFF_INP + 512)       // gated    [row*64+j]
#define OFF_CUR  (OFF_GAT + 512)       // cur      [row*16+c]
#define OFF_SKP  (OFF_CUR + 128)       // skip     [row*384 + i*64 + j] (relu'd)
#define OFF_WP   (OFF_SKP + 8*384)     // W5 partials [ks*1024 + r*128 + jc]
#define OFF_H    (OFF_WP + 4096)       // h        [r*128 + jc]
#define OFF_YP   (OFF_H + 1024)        // per-warp y partials [16]
#define OFF_PV   (OFF_YP + 16)         // prev y per row [8]
#define SMEM_FLOATS (OFF_PV + 8)       // = 53472 floats = 213888 B

__global__ __launch_bounds__(NT, 1)
void decoder_kernel(const float* __restrict__ feat,   // (1024, 24, 15)
                    const float* __restrict__ init,   // (1024, 1)
                    const float* __restrict__ enc,    // (6, 1024, 168, 64)
                    const float* __restrict__ gW1, const float* __restrict__ gb1,
                    const float* __restrict__ gW2, const float* __restrict__ gb2,
                    const float* __restrict__ gW3,
                    const float* __restrict__ gW4, const float* __restrict__ gb4,
                    const float* __restrict__ gW5, const float* __restrict__ gb5,
                    const float* __restrict__ gW6, const float* __restrict__ gb6,
                    float* __restrict__ out)          // (1024, 24)
{
    extern __shared__ float sm[];
    float* const ring = sm + OFF_RING;
    float* const enc5 = sm + OFF_ENC5;
    float* const inp  = sm + OFF_INP;
    float* const gat  = sm + OFF_GAT;
    float* const cur  = sm + OFF_CUR;
    float* const skp  = sm + OFF_SKP;
    float* const wp   = sm + OFF_WP;
    float* const hsm  = sm + OFF_H;
    float* const ypt  = sm + OFF_YP;
    float* const pv   = sm + OFF_PV;

    const int tid  = threadIdx.x;
    const int rg   = tid >> 6;        // row within block (0..7), for 512-wide phases
    const int j    = tid & 63;        // column within row, for 512-wide phases
    const int row0 = blockIdx.x * BROWS;
    const int row  = row0 + rg;

    // ---- load + transpose weights into smem ----
    for (int idx = tid; idx < 8192; idx += NT) {
        int k = idx >> 7, c = idx & 127;              // W[k][c], (64,128) row-major
        sm[OFF_W2T + c*KW + k] = gW2[idx];
        sm[OFF_W3T + c*KW + k] = gW3[idx];
        sm[OFF_W4T + c*KW + k] = gW4[idx];
    }
    for (int idx = tid; idx < 1024; idx += NT) sm[OFF_W1 + idx] = gW1[idx];
    if (tid < 128) {
        sm[OFF_W6 + tid] = gW6[tid];
        sm[OFF_B2 + tid] = gb2[tid];
        sm[OFF_B4 + tid] = gb4[tid];
        sm[OFF_B5 + tid] = gb5[tid];
    }
    if (tid < 64) sm[OFF_B1 + tid] = gb1[tid];
    if (tid == 0) sm[OFF_B6] = gb6[0];
    if (tid < 8)  pv[tid] = init[row0 + tid];
    __syncthreads();

    // Stage-phase thread mapping (first 256 threads): row-pair rp, column-pair (j2, j2+64)
    const int rp  = (tid >> 6) & 3;   // 0..3 (valid when tid < 256)
    const int j2  = tid & 63;
    const int r0s = 2 * rp;
    const int r1s = 2 * rp + 1;

    const float* const w2a = sm + OFF_W2T + j2*KW;
    const float* const w2b = sm + OFF_W2T + (j2+64)*KW;
    const float* const w3a = sm + OFF_W3T + j2*KW;
    const float* const w3b = sm + OFF_W3T + (j2+64)*KW;
    const float* const w4a = sm + OFF_W4T + j2*KW;
    const float* const w4b = sm + OFF_W4T + (j2+64)*KW;
    const float bb2f = sm[OFF_B2 + j2], bb2g = sm[OFF_B2 + 64 + j2];
    const float bb4s = sm[OFF_B4 + j2], bb4r = sm[OFF_B4 + 64 + j2];
    const float bb1  = sm[OFF_B1 + j];

    for (int t = 0; t < T_PRED; t++) {
        // ---- Phase A: stage encoder slices (t<d -> into ring slot; d=32 always) + cur ----
        {
            const int k = j;
            #pragma unroll
            for (int i = 0; i < 5; i++) {
                const int d = 1 << i;
                if (t < d) {
                    float v = enc[(((size_t)i*B_TOTAL + row)*LENC + (LENC + t - d))*FILT + k];
                    ring[((d - 1) + (t & (d - 1)))*512 + rg*64 + k] = v;
                }
            }
            enc5[rg*64 + k] = enc[(((size_t)5*B_TOTAL + row)*LENC + (LENC + t - 32))*FILT + k];
            if (tid < 128) {
                int r = tid >> 4, c = tid & 15;
                cur[tid] = (c == 0) ? pv[r]
                                    : feat[(size_t)(row0 + r)*T_PRED*FEAT + t*FEAT + (c - 1)];
            }
        }
        __syncthreads();

        // ---- Phase B: inputs = tanh(cur @ W1 + b1) ----
        {
            float acc = bb1;
            #pragma unroll
            for (int k = 0; k < 16; k++)
                acc = fmaf(cur[rg*16 + k], sm[OFF_W1 + k*64 + j], acc);
            inp[rg*64 + j] = fast_tanh(acc);
        }
        __syncthreads();

        // ---- dilation stages (sequential), 256 threads, R2C2 register blocking ----
        if (tid < 256) {
            #pragma unroll 1
            for (int i = 0; i < NDIL; i++) {
                const int d = 1 << i;
                const float* base = (i < 5) ? (ring + ((d - 1) + (t & (d - 1)))*512)
                                            : enc5;
                const float* st0 = base + r0s*64;
                const float* st1 = base + r1s*64;
                const float* in0 = inp + r0s*64;
                const float* in1 = inp + r1s*64;

                // dilated[j2], dilated[j2+64] for 2 rows = state@W2 + b2 + inputs@W3
                float f0 = bb2f, g0 = bb2g, f1 = bb2f, g1 = bb2g;
                #pragma unroll
                for (int k = 0; k < 64; k += 4) {
                    float4 wa = *(const float4*)(w2a + k);
                    float4 wb = *(const float4*)(w2b + k);
                    float4 wc = *(const float4*)(w3a + k);
                    float4 wd = *(const float4*)(w3b + k);
                    float4 s0 = *(const float4*)(st0 + k);
                    float4 i0 = *(const float4*)(in0 + k);
                    float4 s1 = *(const float4*)(st1 + k);
                    float4 i1 = *(const float4*)(in1 + k);
                    dot4(f0, s0, wa);  dot4(f0, i0, wc);
                    dot4(g0, s0, wb);  dot4(g0, i0, wd);
                    dot4(f1, s1, wa);  dot4(f1, i1, wc);
                    dot4(g1, s1, wb);  dot4(g1, i1, wd);
                }
                gat[r0s*64 + j2] = fast_tanh(f0) * fast_sigmoid(g0);
                gat[r1s*64 + j2] = fast_tanh(f1) * fast_sigmoid(g1);
                BAR256();

                // out = gated@W4 + b4 ; skips/residuals split
                float s0a = bb4s, res0 = bb4r, s1a = bb4s, res1 = bb4r;
                const float* g0r = gat + r0s*64;
                const float* g1r = gat + r1s*64;
                #pragma unroll
                for (int k = 0; k < 64; k += 4) {
                    float4 wa = *(const float4*)(w4a + k);
                    float4 wb = *(const float4*)(w4b + k);
                    float4 g0v = *(const float4*)(g0r + k);
                    float4 g1v = *(const float4*)(g1r + k);
                    dot4(s0a,  g0v, wa);
                    dot4(res0, g0v, wb);
                    dot4(s1a,  g1v, wa);
                    dot4(res1, g1v, wb);
                }
                float ni0 = inp[r0s*64 + j2] + res0;
                float ni1 = inp[r1s*64 + j2] + res1;
                skp[r0s*384 + i*64 + j2] = fmaxf(s0a, 0.0f);
                skp[r1s*384 + i*64 + j2] = fmaxf(s1a, 0.0f);
                if (i < 5) {
                    float* slot = ring + ((d - 1) + (t & (d - 1)))*512;
                    slot[r0s*64 + j2] = ni0;
                    slot[r1s*64 + j2] = ni1;
                }
                inp[r0s*64 + j2] = ni0;
                inp[r1s*64 + j2] = ni1;
                BAR256();
            }
        }
        __syncthreads();

        // ---- Phase E: h_partial = skip @ W5 (128 threads: 4 cols x 4 k-segments) ----
        if (tid < 128) {
            const int jc4 = (tid & 31) * 4;   // output columns [jc4, jc4+4)
            const int ks  = tid >> 5;         // k-segment 0..3 (96 k each)
            const int kb  = ks * 96;
            float4 acc[8];
            #pragma unroll
            for (int r = 0; r < 8; r++) acc[r] = make_float4(0.f, 0.f, 0.f, 0.f);
            #pragma unroll 4
            for (int kq = 0; kq < 96; kq += 4) {
                const int k = kb + kq;
                float4 w0 = *(const float4*)(gW5 + (size_t)(k + 0)*128 + jc4);
                float4 w1 = *(const float4*)(gW5 + (size_t)(k + 1)*128 + jc4);
                float4 w2 = *(const float4*)(gW5 + (size_t)(k + 2)*128 + jc4);
                float4 w3 = *(const float4*)(gW5 + (size_t)(k + 3)*128 + jc4);
                #pragma unroll
                for (int r = 0; r < 8; r++) {
                    float4 sv = *(const float4*)(skp + r*384 + k);
                    fma4s(acc[r], sv.x, w0);
                    fma4s(acc[r], sv.y, w1);
                    fma4s(acc[r], sv.z, w2);
                    fma4s(acc[r], sv.w, w3);
                }
            }
            #pragma unroll
            for (int r = 0; r < 8; r++)
                *(float4*)(wp + ks*1024 + r*128 + jc4) = acc[r];
        }
        __syncthreads();

        // ---- Phase F: reduce partials, + b5, relu -> h ----
        #pragma unroll
        for (int o = tid; o < 1024; o += NT) {
            float v = wp[o] + wp[1024 + o] + wp[2048 + o] + wp[3072 + o] + sm[OFF_B5 + (o & 127)];
            hsm[o] = fmaxf(v, 0.0f);
        }
        __syncthreads();

        // ---- Phase G: y = h @ W6 + b6 ----
        {
            float v = hsm[rg*128 + j]       * sm[OFF_W6 + j]
                    + hsm[rg*128 + 64 + j]  * sm[OFF_W6 + 64 + j];
            #pragma unroll
            for (int off = 16; off; off >>= 1)
                v += __shfl_down_sync(0xffffffffu, v, off);
            if ((tid & 31) == 0) ypt[tid >> 5] = v;
        }
        __syncthreads();
        if (tid < 8) {
            float y = ypt[2*tid] + ypt[2*tid + 1] + sm[OFF_B6];
            pv[tid] = y;
            out[(size_t)(row0 + tid)*T_PRED + t] = y;
        }
        __syncthreads();
    }
}

extern "C" void kernel_launch(void* const* d_in, const int* in_sizes, int n_in,
                              void* d_out, int out_size) {
    const float* feat = (const float*)d_in[0];   // decoder_features
    const float* init = (const float*)d_in[1];   // decoder_init_input
    const float* enc  = (const float*)d_in[2];   // encoder_states
    const float* W1 = (const float*)d_in[3];
    const float* b1 = (const float*)d_in[4];
    const float* W2 = (const float*)d_in[5];
    const float* b2 = (const float*)d_in[6];
    const float* W3 = (const float*)d_in[7];
    const float* W4 = (const float*)d_in[8];
    const float* b4 = (const float*)d_in[9];
    const float* W5 = (const float*)d_in[10];
    const float* b5 = (const float*)d_in[11];
    const float* W6 = (const float*)d_in[12];
    const float* b6 = (const float*)d_in[13];
    float* outp = (float*)d_out;

    const size_t smem_bytes = (size_t)SMEM_FLOATS * sizeof(float);
    cudaFuncSetAttribute(decoder_kernel,
                         cudaFuncAttributeMaxDynamicSharedMemorySize,
                         (int)smem_bytes);
    decoder_kernel<<<NBLK, NT, smem_bytes>>>(feat, init, enc,
                                             W1, b1, W2, b2, W3, W4, b4,
                                             W5, b5, W6, b6, outp);
}

// round 16
// speedup vs baseline: 1.1833x; 1.1833x over previous
#include <cuda_runtime.h>
#include <cstdint>

// Problem constants
#define B_TOTAL 1024
#define T_PRED  24
#define FEAT    15
#define FILT    64
#define LENC    168
#define NDIL    6

// Kernel config
#define BROWS   8
#define NBLK    (B_TOTAL / BROWS)   // 128
#define NT      256
#define KW      68    // padded row stride (floats) for transposed weights

typedef unsigned long long u64;

static __device__ __forceinline__ float fast_tanh(float x) {
    float e;
    asm("ex2.approx.f32 %0, %1;" : "=f"(e) : "f"(x * 2.8853900817779268f));
    float r;
    asm("rcp.approx.f32 %0, %1;" : "=f"(r) : "f"(e + 1.0f));
    return fmaf(-2.0f, r, 1.0f);
}
static __device__ __forceinline__ float fast_sigmoid(float x) {
    float e;
    asm("ex2.approx.f32 %0, %1;" : "=f"(e) : "f"(-x * 1.4426950408889634f));
    float r;
    asm("rcp.approx.f32 %0, %1;" : "=f"(r) : "f"(e + 1.0f));
    return r;
}

// packed f32x2 helpers
static __device__ __forceinline__ void fma2(u64& d, u64 a, u64 b) {
    asm("fma.rn.f32x2 %0, %1, %2, %0;" : "+l"(d) : "l"(a), "l"(b));
}
static __device__ __forceinline__ u64 pack2(float lo, float hi) {
    u64 r; asm("mov.b64 %0, {%1, %2};" : "=l"(r) : "f"(lo), "f"(hi)); return r;
}
static __device__ __forceinline__ float sum2(u64 v) {
    float lo, hi; asm("mov.b64 {%0, %1}, %2;" : "=f"(lo), "=f"(hi) : "l"(v));
    return lo + hi;
}

#define BAR128() asm volatile("bar.sync 1, 128;" ::: "memory")

// W5 pre-packed: [kpair][col][parity]  (parity = k & 1)
__device__ float g_W5P[384 * 128];

__global__ void w5_pack_kernel(const float* __restrict__ gW5) {
    int e = blockIdx.x * blockDim.x + threadIdx.x;
    if (e < 384 * 128) {
        int k = e >> 7, c = e & 127;
        g_W5P[(k >> 1) * 256 + c * 2 + (k & 1)] = gW5[e];
    }
}

// ---- shared memory layout (float offsets) ----
#define OFF_W2T  0
#define OFF_W3T  (128*KW)
#define OFF_W4T  (2*128*KW)
#define OFF_W1   (3*128*KW)
#define OFF_W6   (OFF_W1 + 1024)
#define OFF_B1   (OFF_W6 + 128)
#define OFF_B2   (OFF_B1 + 64)
#define OFF_B4   (OFF_B2 + 128)
#define OFF_B5   (OFF_B4 + 128)
#define OFF_B6   (OFF_B5 + 128)
#define OFF_RING (OFF_B6 + 8)          // 31 slices * 512 floats
#define OFF_ENC5 (OFF_RING + 31*512)
#define OFF_INP  (OFF_ENC5 + 512)
#define OFF_GAT  (OFF_INP + 512)
#define OFF_CUR  (OFF_GAT + 512)
#define OFF_SKP  (OFF_CUR + 128)       // skip [row*384 + i*64 + j]
#define OFF_WP   (OFF_SKP + 8*384)     // W5 partials [ks*1024 + r*128 + c]
#define OFF_H    (OFF_WP + 4096)
#define OFF_PV   (OFF_H + 1024)
#define SMEM_FLOATS (OFF_PV + 8)

__global__ __launch_bounds__(NT, 1)
void decoder_kernel(const float* __restrict__ feat,   // (1024, 24, 15)
                    const float* __restrict__ init,   // (1024, 1)
                    const float* __restrict__ enc,    // (6, 1024, 168, 64)
                    const float* __restrict__ gW1, const float* __restrict__ gb1,
                    const float* __restrict__ gW2, const float* __restrict__ gb2,
                    const float* __restrict__ gW3,
                    const float* __restrict__ gW4, const float* __restrict__ gb4,
                    const float* __restrict__ gb5,
                    const float* __restrict__ gW6, const float* __restrict__ gb6,
                    float* __restrict__ out)          // (1024, 24)
{
    extern __shared__ float sm[];
    float* const ring = sm + OFF_RING;
    float* const enc5 = sm + OFF_ENC5;
    float* const inp  = sm + OFF_INP;
    float* const gat  = sm + OFF_GAT;
    float* const cur  = sm + OFF_CUR;
    float* const skp  = sm + OFF_SKP;
    float* const wp   = sm + OFF_WP;
    float* const hsm  = sm + OFF_H;
    float* const pv   = sm + OFF_PV;

    const int tid  = threadIdx.x;
    const int row0 = blockIdx.x * BROWS;

    // ---- one-time: load + transpose weights into smem ----
    for (int idx = tid; idx < 8192; idx += NT) {
        int k = idx >> 7, c = idx & 127;
        sm[OFF_W2T + c*KW + k] = gW2[idx];
        sm[OFF_W3T + c*KW + k] = gW3[idx];
        sm[OFF_W4T + c*KW + k] = gW4[idx];
    }
    for (int idx = tid; idx < 1024; idx += NT) sm[OFF_W1 + idx] = gW1[idx];
    if (tid < 128) {
        sm[OFF_W6 + tid] = gW6[tid];
        sm[OFF_B2 + tid] = gb2[tid];
        sm[OFF_B4 + tid] = gb4[tid];
        sm[OFF_B5 + tid] = gb5[tid];
    }
    if (tid >= 128 && tid < 192) sm[OFF_B1 + tid - 128] = gb1[tid - 128];
    if (tid == 224) sm[OFF_B6] = gb6[0];
    if (tid >= 240 && tid < 248) pv[tid - 240] = init[row0 + tid - 240];
    __syncthreads();

    // stage-phase thread mapping (tid < 128): row-quad rq, column pair (j2, j2+64)
    const int j2 = tid & 63;
    const int rq = (tid >> 6) & 1;
    const int rb = rq * 4;

    const float* const w2a = sm + OFF_W2T + j2*KW;
    const float* const w2b = sm + OFF_W2T + (j2+64)*KW;
    const float* const w3a = sm + OFF_W3T + j2*KW;
    const float* const w3b = sm + OFF_W3T + (j2+64)*KW;
    const float* const w4a = sm + OFF_W4T + j2*KW;
    const float* const w4b = sm + OFF_W4T + (j2+64)*KW;
    const float bb2f = sm[OFF_B2 + j2], bb2g = sm[OFF_B2 + 64 + j2];
    const float bb4s = sm[OFF_B4 + j2], bb4r = sm[OFF_B4 + 64 + j2];

    // encoder d=32 prefetch registers (threads 128..255 own enc5; 4 elems each)
    float pf0 = 0.f, pf1 = 0.f, pf2 = 0.f, pf3 = 0.f;
    if (tid >= 128) {   // prefetch for t = 0
        const int o = tid - 128;
        const int t0 = 0;
        #define ENC5_ADDR(o_, t_) \
            (((size_t)5*B_TOTAL + row0 + ((o_) >> 6))*LENC + (LENC + (t_) - 32))*FILT + ((o_) & 63)
        pf0 = enc[ENC5_ADDR(o,       t0)];
        pf1 = enc[ENC5_ADDR(o + 128, t0)];
        pf2 = enc[ENC5_ADDR(o + 256, t0)];
        pf3 = enc[ENC5_ADDR(o + 384, t0)];
    }

    for (int t = 0; t < T_PRED; t++) {
        // ---- Phase A: stage encoder slices + cur ----
        if (tid >= 128) {
            const int o = tid - 128;
            enc5[o]       = pf0;
            enc5[o + 128] = pf1;
            enc5[o + 256] = pf2;
            enc5[o + 384] = pf3;
        } else {
            #pragma unroll
            for (int i = 0; i < 5; i++) {
                const int d = 1 << i;
                if (t < d) {
                    const int sl = (d - 1) + (t & (d - 1));
                    for (int o = tid; o < 512; o += 128) {
                        int rg = o >> 6, k = o & 63;
                        ring[sl*512 + o] =
                            enc[(((size_t)i*B_TOTAL + row0 + rg)*LENC + (LENC + t - d))*FILT + k];
                    }
                }
            }
            {   // cur: [r][16] = {prev_y, feat[...]}
                int r = tid >> 4, c = tid & 15;
                cur[tid] = (c == 0) ? pv[r]
                                    : feat[(size_t)(row0 + r)*T_PRED*FEAT + t*FEAT + (c - 1)];
            }
        }
        __syncthreads();

        // ---- Phase B: inputs = tanh(cur @ W1 + b1) ----
        #pragma unroll
        for (int o = tid; o < 512; o += NT) {
            int rg = o >> 6, jj = o & 63;
            float acc = sm[OFF_B1 + jj];
            #pragma unroll
            for (int k = 0; k < 16; k++)
                acc = fmaf(cur[rg*16 + k], sm[OFF_W1 + k*64 + jj], acc);
            inp[o] = fast_tanh(acc);
        }
        __syncthreads();

        // ---- dilation stages: 128 threads, R4C2, FFMA2 ----
        if (tid < 128) {
            #pragma unroll 1
            for (int i = 0; i < NDIL; i++) {
                const int d  = 1 << i;
                const int sl = (d - 1) + (t & (d - 1));
                const float* base = (i < 5) ? (ring + sl*512) : enc5;

                u64 F[4], G[4];
                #pragma unroll
                for (int r = 0; r < 4; r++) { F[r] = pack2(bb2f, 0.f); G[r] = pack2(bb2g, 0.f); }

                #pragma unroll
                for (int k = 0; k < 64; k += 4) {
                    ulonglong2 wa = *(const ulonglong2*)(w2a + k);
                    ulonglong2 wb = *(const ulonglong2*)(w2b + k);
                    ulonglong2 wc = *(const ulonglong2*)(w3a + k);
                    ulonglong2 wd = *(const ulonglong2*)(w3b + k);
                    #pragma unroll
                    for (int r = 0; r < 4; r++) {
                        ulonglong2 sv = *(const ulonglong2*)(base + (rb + r)*64 + k);
                        ulonglong2 iv = *(const ulonglong2*)(inp  + (rb + r)*64 + k);
                        fma2(F[r], sv.x, wa.x); fma2(F[r], sv.y, wa.y);
                        fma2(F[r], iv.x, wc.x); fma2(F[r], iv.y, wc.y);
                        fma2(G[r], sv.x, wb.x); fma2(G[r], sv.y, wb.y);
                        fma2(G[r], iv.x, wd.x); fma2(G[r], iv.y, wd.y);
                    }
                }
                #pragma unroll
                for (int r = 0; r < 4; r++)
                    gat[(rb + r)*64 + j2] = fast_tanh(sum2(F[r])) * fast_sigmoid(sum2(G[r]));
                BAR128();

                u64 S[4], R[4];
                #pragma unroll
                for (int r = 0; r < 4; r++) { S[r] = pack2(bb4s, 0.f); R[r] = pack2(bb4r, 0.f); }

                #pragma unroll
                for (int k = 0; k < 64; k += 4) {
                    ulonglong2 wa = *(const ulonglong2*)(w4a + k);
                    ulonglong2 wb = *(const ulonglong2*)(w4b + k);
                    #pragma unroll
                    for (int r = 0; r < 4; r++) {
                        ulonglong2 gv = *(const ulonglong2*)(gat + (rb + r)*64 + k);
                        fma2(S[r], gv.x, wa.x); fma2(S[r], gv.y, wa.y);
                        fma2(R[r], gv.x, wb.x); fma2(R[r], gv.y, wb.y);
                    }
                }
                float* slot = ring + sl*512;
                #pragma unroll
                for (int r = 0; r < 4; r++) {
                    const int e = (rb + r)*64 + j2;
                    float ni = inp[e] + sum2(R[r]);
                    skp[(rb + r)*384 + i*64 + j2] = fmaxf(sum2(S[r]), 0.0f);
                    if (i < 5) slot[e] = ni;
                    inp[e] = ni;
                }
                BAR128();
            }
        } else if (t + 1 < T_PRED) {
            // warps 4-7: prefetch next step's enc5 slice (DRAM latency hidden behind stages)
            const int o = tid - 128;
            pf0 = enc[ENC5_ADDR(o,       t + 1)];
            pf1 = enc[ENC5_ADDR(o + 128, t + 1)];
            pf2 = enc[ENC5_ADDR(o + 256, t + 1)];
            pf3 = enc[ENC5_ADDR(o + 384, t + 1)];
        }
        __syncthreads();

        // ---- Phase E: skip @ W5 (128 threads: 64 col-pairs x 2 k-segments, FFMA2) ----
        if (tid < 128) {
            const int q  = tid & 63;      // col pair -> cols 2q, 2q+1
            const int ks = tid >> 6;      // k-segment (192 k each)
            const u64* w5p = (const u64*)g_W5P;   // [kpair][col] u64 = (W5[2kp][c], W5[2kp+1][c])

            u64 acc0[8], acc1[8];
            #pragma unroll
            for (int r = 0; r < 8; r++) { acc0[r] = 0ull; acc1[r] = 0ull; }

            const int kp0 = ks * 96;
            #pragma unroll 4
            for (int kp = kp0; kp < kp0 + 96; kp += 2) {
                ulonglong2 w0 = *(const ulonglong2*)(w5p + (size_t)kp*128 + 2*q);
                ulonglong2 w1 = *(const ulonglong2*)(w5p + (size_t)(kp + 1)*128 + 2*q);
                const int k4 = kp * 2;
                #pragma unroll
                for (int r = 0; r < 8; r++) {
                    ulonglong2 sv = *(const ulonglong2*)(skp + r*384 + k4);
                    fma2(acc0[r], sv.x, w0.x); fma2(acc1[r], sv.x, w0.y);
                    fma2(acc0[r], sv.y, w1.x); fma2(acc1[r], sv.y, w1.y);
                }
            }
            #pragma unroll
            for (int r = 0; r < 8; r++)
                *(float2*)(wp + ks*1024 + r*128 + 2*q) = make_float2(sum2(acc0[r]), sum2(acc1[r]));
        }
        __syncthreads();

        // ---- Phase F: reduce 2 partials, + b5, relu ----
        #pragma unroll
        for (int o = tid; o < 1024; o += NT)
            hsm[o] = fmaxf(wp[o] + wp[1024 + o] + sm[OFF_B5 + (o & 127)], 0.0f);
        __syncthreads();

        // ---- Phase G: y = h @ W6 + b6 (one warp per row) ----
        {
            const int w = tid >> 5, lane = tid & 31;
            float v = hsm[w*128 + lane]      * sm[OFF_W6 + lane]
                    + hsm[w*128 + 32 + lane] * sm[OFF_W6 + 32 + lane]
                    + hsm[w*128 + 64 + lane] * sm[OFF_W6 + 64 + lane]
                    + hsm[w*128 + 96 + lane] * sm[OFF_W6 + 96 + lane];
            #pragma unroll
            for (int off = 16; off; off >>= 1)
                v += __shfl_down_sync(0xffffffffu, v, off);
            if (lane == 0) {
                float y = v + sm[OFF_B6];
                pv[w] = y;
                out[(size_t)(row0 + w)*T_PRED + t] = y;
            }
        }
        __syncthreads();
    }
}

extern "C" void kernel_launch(void* const* d_in, const int* in_sizes, int n_in,
                              void* d_out, int out_size) {
    const float* feat = (const float*)d_in[0];
    const float* init = (const float*)d_in[1];
    const float* enc  = (const float*)d_in[2];
    const float* W1 = (const float*)d_in[3];
    const float* b1 = (const float*)d_in[4];
    const float* W2 = (const float*)d_in[5];
    const float* b2 = (const float*)d_in[6];
    const float* W3 = (const float*)d_in[7];
    const float* W4 = (const float*)d_in[8];
    const float* b4 = (const float*)d_in[9];
    const float* W5 = (const float*)d_in[10];
    const float* b5 = (const float*)d_in[11];
    const float* W6 = (const float*)d_in[12];
    const float* b6 = (const float*)d_in[13];
    float* outp = (float*)d_out;

    w5_pack_kernel<<<48, 1024>>>(W5);

    const size_t smem_bytes = (size_t)SMEM_FLOATS * sizeof(float);
    cudaFuncSetAttribute(decoder_kernel,
                         cudaFuncAttributeMaxDynamicSharedMemorySize,
                         (int)smem_bytes);
    decoder_kernel<<<NBLK, NT, smem_bytes>>>(feat, init, enc,
                                             W1, b1, W2, b2, W3, W4, b4,
                                             b5, W6, b6, outp);
}